// round 5
// baseline (speedup 1.0000x reference)
#include <cuda_runtime.h>
#include <cstdint>

#define N_NODES 100000
#define N_EDGES 1600000
#define D 64
#define CAP 64            // per-node in-edge bucket capacity (Poisson(16), max ~45)
#define OVF_CAP 8192      // overflow edge list (statistically never used)

// Scratch (__device__ globals: allocation-free per harness rules)
__device__ int   g_is64;                          // edge_index dtype flag
__device__ float g_deg[N_NODES];                  // degree, then dinv in place
__device__ int   g_cnt[N_NODES];                  // bucket fill counters
__device__ int2  g_bucket[(size_t)N_NODES * CAP]; // {row, bitcast(w)}
__device__ int   g_ovf_cnt;
__device__ int   g_ovf[OVF_CAP];                  // overflow edge ids
__device__ __align__(16) float g_tx1[(size_t)N_NODES * D];

// ---------------------------------------------------------------------------
// K0: detect edge_index dtype (int64 => odd int32 words are all zero).
// ---------------------------------------------------------------------------
__global__ void detect_kernel(const int* __restrict__ ei) {
    __shared__ int any;
    if (threadIdx.x == 0) any = 0;
    __syncthreads();
    for (int i = 1 + 2 * threadIdx.x; i < 4096; i += 2 * blockDim.x)
        if (ei[i] != 0) atomicOr(&any, 1);
    __syncthreads();
    if (threadIdx.x == 0) g_is64 = any ? 0 : 1;
}

__device__ __forceinline__ void load_edge(const void* ei, int E, int e,
                                          int& r, int& c) {
    if (g_is64) {
        const long long* p = (const long long*)ei;
        r = (int)p[e];
        c = (int)p[(size_t)E + e];
    } else {
        const int* p = (const int*)ei;
        r = p[e];
        c = p[E + e];
    }
}

// ---------------------------------------------------------------------------
// K1: zero deg + counters
// ---------------------------------------------------------------------------
__global__ void zero_kernel() {
    int i = blockIdx.x * blockDim.x + threadIdx.x;
    if (i < N_NODES) { g_deg[i] = 0.f; g_cnt[i] = 0; }
    if (i == 0) g_ovf_cnt = 0;
}

// ---------------------------------------------------------------------------
// K2: single edge pass — deg[row] += w AND append {row, w} to col's bucket.
// ---------------------------------------------------------------------------
__global__ void edge_pass_kernel(const void* __restrict__ ei,
                                 const float* __restrict__ ew, int E) {
    int e = blockIdx.x * blockDim.x + threadIdx.x;
    if (e >= E) return;
    int r, c;
    load_edge(ei, E, e, r, c);
    float w = __ldg(&ew[e]);
    atomicAdd(&g_deg[r], w);
    int pos = atomicAdd(&g_cnt[c], 1);
    if (pos < CAP) {
        g_bucket[(size_t)c * CAP + pos] = make_int2(r, __float_as_int(w));
    } else {
        int o = atomicAdd(&g_ovf_cnt, 1);
        if (o < OVF_CAP) g_ovf[o] = e;
    }
}

// ---------------------------------------------------------------------------
// K3: deg -> dinv (in place)
// ---------------------------------------------------------------------------
__global__ void dinv_kernel() {
    int i = blockIdx.x * blockDim.x + threadIdx.x;
    if (i < N_NODES) {
        float d = g_deg[i];
        g_deg[i] = (d > 0.f) ? rsqrtf(d) : 0.f;
    }
}

// ---------------------------------------------------------------------------
// K4: gather. One warp per destination node; lanes own columns lane, lane+32.
// norm computed inline: -dinv[row] * w * dinv[col].
// ---------------------------------------------------------------------------
__global__ void __launch_bounds__(256)
gather_kernel(const float* __restrict__ x) {
    int warp_in_block = threadIdx.x >> 5;
    int lane = threadIdx.x & 31;
    int node = blockIdx.x * (blockDim.x >> 5) + warp_in_block;
    if (node >= N_NODES) return;

    int n = g_cnt[node];
    if (n > CAP) n = CAP;
    float dinv_c = g_deg[node];          // holds dinv now

    float a0 = 0.f, a1 = 0.f;
    const int2* bk = &g_bucket[(size_t)node * CAP];

    for (int base = 0; base < n; base += 32) {
        int m = n - base; if (m > 32) m = 32;
        int   r_l  = 0;
        float nm_l = 0.f;
        if (lane < m) {
            int2 ed = bk[base + lane];
            r_l  = ed.x;
            nm_l = -g_deg[ed.x] * __int_as_float(ed.y) * dinv_c;
        }
        #pragma unroll 4
        for (int j = 0; j < m; j++) {
            int   r  = __shfl_sync(0xffffffffu, r_l, j);
            float nm = __shfl_sync(0xffffffffu, nm_l, j);
            const float* xr = x + (size_t)r * D;
            a0 = fmaf(nm, __ldg(xr + lane),      a0);
            a1 = fmaf(nm, __ldg(xr + 32 + lane), a1);
        }
    }
    float* t = g_tx1 + (size_t)node * D;
    t[lane]      = a0;
    t[lane + 32] = a1;
}

// ---------------------------------------------------------------------------
// K5: overflow drain (statistically empty).
// ---------------------------------------------------------------------------
__global__ void overflow_kernel(const void* __restrict__ ei,
                                const float* __restrict__ ew,
                                const float* __restrict__ x, int E) {
    int i = blockIdx.x * blockDim.x + threadIdx.x;
    int cnt = g_ovf_cnt;
    if (cnt > OVF_CAP) cnt = OVF_CAP;
    if (i >= cnt) return;
    int e = g_ovf[i];
    int r, c;
    load_edge(ei, E, e, r, c);
    float w = __ldg(&ew[e]);
    float norm = -g_deg[r] * w * g_deg[c];
    const float* xr = x + (size_t)r * D;
    float* t = g_tx1 + (size_t)c * D;
    for (int j = 0; j < D; j++) atomicAdd(&t[j], norm * __ldg(&xr[j]));
}

// ---------------------------------------------------------------------------
// packed fp32x2 FMA (Blackwell FFMA2 — only reachable via PTX)
// acc = w * s + acc, elementwise on 2-wide packs.
// ---------------------------------------------------------------------------
__device__ __forceinline__ void fma2(unsigned long long& acc,
                                     unsigned long long w,
                                     unsigned long long s) {
    asm("fma.rn.f32x2 %0, %1, %2, %0;" : "+l"(acc) : "l"(w), "l"(s));
}
__device__ __forceinline__ unsigned long long pack2(float v) {
    unsigned long long r;
    asm("mov.b64 %0, {%1, %1};" : "=l"(r) : "f"(v));
    return r;
}

// ---------------------------------------------------------------------------
// K6: out = x @ W0 + Tx1 @ W1 + b.  One thread per node row.
// Inner product via packed f32x2 FMA: 64 FFMA2 + 32 LDS.128 per k-step.
// ---------------------------------------------------------------------------
__global__ void __launch_bounds__(256)
gemm_kernel(const float* __restrict__ x,
            const float* __restrict__ W0,
            const float* __restrict__ W1,
            const float* __restrict__ b,
            float* __restrict__ out, int N) {
    __shared__ __align__(16) float sW0[D * D];
    __shared__ __align__(16) float sW1[D * D];
    __shared__ __align__(16) float sb[D];

    for (int i = threadIdx.x; i < D * D; i += blockDim.x) {
        sW0[i] = W0[i];
        sW1[i] = W1[i];
    }
    if (threadIdx.x < D) sb[threadIdx.x] = b[threadIdx.x];
    __syncthreads();

    int row = blockIdx.x * blockDim.x + threadIdx.x;
    if (row >= N) return;

    // 32 packed accumulators covering cols (2j, 2j+1), init = bias
    unsigned long long acc[D / 2];
    const unsigned long long* sb2 = (const unsigned long long*)sb;
#pragma unroll
    for (int j = 0; j < D / 2; j++) acc[j] = sb2[j];

    const float* xr = x + (size_t)row * D;
    const float* tr = g_tx1 + (size_t)row * D;

#pragma unroll 4
    for (int k = 0; k < D; k++) {
        unsigned long long xx = pack2(__ldg(&xr[k]));
        unsigned long long tt = pack2(tr[k]);
        const ulonglong2* w0r = (const ulonglong2*)&sW0[k * D];
        const ulonglong2* w1r = (const ulonglong2*)&sW1[k * D];
#pragma unroll
        for (int j = 0; j < D / 4; j++) {
            ulonglong2 w0 = w0r[j];
            ulonglong2 w1 = w1r[j];
            fma2(acc[2 * j],     w0.x, xx);
            fma2(acc[2 * j + 1], w0.y, xx);
            fma2(acc[2 * j],     w1.x, tt);
            fma2(acc[2 * j + 1], w1.y, tt);
        }
    }

    ulonglong2* o = (ulonglong2*)(out + (size_t)row * D);
#pragma unroll
    for (int j = 0; j < D / 4; j++)
        o[j] = make_ulonglong2(acc[2 * j], acc[2 * j + 1]);
}

// ---------------------------------------------------------------------------
// Launch
// ---------------------------------------------------------------------------
extern "C" void kernel_launch(void* const* d_in, const int* in_sizes, int n_in,
                              void* d_out, int out_size) {
    const float* x  = (const float*)d_in[0];
    const void*  ei = d_in[1];
    const float* ew = (const float*)d_in[2];
    const float* W0 = (const float*)d_in[3];
    const float* W1 = (const float*)d_in[4];
    const float* b  = (const float*)d_in[5];
    float*       out = (float*)d_out;

    int E = in_sizes[2];
    int N = in_sizes[0] / D;

    detect_kernel<<<1, 256>>>((const int*)ei);
    zero_kernel<<<(N_NODES + 255) / 256, 256>>>();
    edge_pass_kernel<<<(E + 255) / 256, 256>>>(ei, ew, E);
    dinv_kernel<<<(N_NODES + 255) / 256, 256>>>();
    {
        int warps_per_block = 256 / 32;
        int blocks = (N_NODES + warps_per_block - 1) / warps_per_block;
        gather_kernel<<<blocks, 256>>>(x);
    }
    overflow_kernel<<<(OVF_CAP + 255) / 256, 256>>>(ei, ew, x, E);
    gemm_kernel<<<(N + 255) / 256, 256>>>(x, W0, W1, b, out, N);
}

// round 6
// speedup vs baseline: 1.1534x; 1.1534x over previous
#include <cuda_runtime.h>
#include <cstdint>

#define N_NODES 100000
#define D 64
#define CAP 64            // per-node in-edge bucket capacity (Poisson(16), max ~45)
#define OVF_CAP 8192      // overflow edge list (statistically never used)

// Scratch (__device__ globals: allocation-free per harness rules)
__device__ int   g_is64;                          // edge_index dtype flag
__device__ float g_deg[N_NODES];                  // raw weighted out-degree
__device__ int   g_cnt[N_NODES];                  // bucket fill counters
__device__ int2  g_bucket[(size_t)N_NODES * CAP]; // {row, bitcast(w)}
__device__ int   g_ovf_cnt;
__device__ int   g_ovf[OVF_CAP];                  // overflow edge ids
__device__ __align__(16) float g_tx1[(size_t)N_NODES * D];

__device__ __forceinline__ float dinv_of(float d) {
    return (d > 0.f) ? rsqrtf(d) : 0.f;
}

__device__ __forceinline__ void load_edge(const void* ei, int E, int e,
                                          int& r, int& c) {
    if (g_is64) {
        const long long* p = (const long long*)ei;
        r = (int)p[e];
        c = (int)p[(size_t)E + e];
    } else {
        const int* p = (const int*)ei;
        r = p[e];
        c = p[E + e];
    }
}

// ---------------------------------------------------------------------------
// K1: zero deg + counters; block 0 also detects edge_index dtype
// (int64 => odd int32 words of the first 2048 entries are all zero).
// ---------------------------------------------------------------------------
__global__ void zero_detect_kernel(const int* __restrict__ ei) {
    int i = blockIdx.x * blockDim.x + threadIdx.x;
    if (i < N_NODES) { g_deg[i] = 0.f; g_cnt[i] = 0; }
    if (i == 0) g_ovf_cnt = 0;
    if (blockIdx.x == 0) {
        __shared__ int any;
        if (threadIdx.x == 0) any = 0;
        __syncthreads();
        int loc = 0;
        for (int k = 1 + 2 * threadIdx.x; k < 4096; k += 2 * blockDim.x)
            loc |= ei[k];
        if (loc) atomicOr(&any, 1);
        __syncthreads();
        if (threadIdx.x == 0) g_is64 = any ? 0 : 1;
    }
}

// ---------------------------------------------------------------------------
// K2: single edge pass — deg[row] += w AND append {row, w} to col's bucket.
// ---------------------------------------------------------------------------
__global__ void edge_pass_kernel(const void* __restrict__ ei,
                                 const float* __restrict__ ew, int E) {
    int e = blockIdx.x * blockDim.x + threadIdx.x;
    if (e >= E) return;
    int r, c;
    load_edge(ei, E, e, r, c);
    float w = __ldg(&ew[e]);
    atomicAdd(&g_deg[r], w);
    int pos = atomicAdd(&g_cnt[c], 1);
    if (pos < CAP) {
        g_bucket[(size_t)c * CAP + pos] = make_int2(r, __float_as_int(w));
    } else {
        int o = atomicAdd(&g_ovf_cnt, 1);
        if (o < OVF_CAP) g_ovf[o] = e;
    }
}

// ---------------------------------------------------------------------------
// K3: gather. One warp per destination node; lanes own columns lane, lane+32.
// dinv computed inline from raw degrees (MUFU cost is noise).
// ---------------------------------------------------------------------------
__global__ void __launch_bounds__(256)
gather_kernel(const float* __restrict__ x) {
    int warp_in_block = threadIdx.x >> 5;
    int lane = threadIdx.x & 31;
    int node = blockIdx.x * (blockDim.x >> 5) + warp_in_block;
    if (node >= N_NODES) return;

    int n = g_cnt[node];
    if (n > CAP) n = CAP;
    float dinv_c = dinv_of(g_deg[node]);

    float a0 = 0.f, a1 = 0.f;
    const int2* bk = &g_bucket[(size_t)node * CAP];

    for (int base = 0; base < n; base += 32) {
        int m = n - base; if (m > 32) m = 32;
        int   r_l  = 0;
        float nm_l = 0.f;
        if (lane < m) {
            int2 ed = bk[base + lane];
            r_l  = ed.x;
            nm_l = -dinv_of(g_deg[ed.x]) * __int_as_float(ed.y) * dinv_c;
        }
        #pragma unroll 4
        for (int j = 0; j < m; j++) {
            int   r  = __shfl_sync(0xffffffffu, r_l, j);
            float nm = __shfl_sync(0xffffffffu, nm_l, j);
            const float* xr = x + (size_t)r * D;
            a0 = fmaf(nm, __ldg(xr + lane),      a0);
            a1 = fmaf(nm, __ldg(xr + 32 + lane), a1);
        }
    }
    float* t = g_tx1 + (size_t)node * D;
    t[lane]      = a0;
    t[lane + 32] = a1;
}

// ---------------------------------------------------------------------------
// K4: overflow drain (statistically empty) — atomics into g_tx1.
// ---------------------------------------------------------------------------
__global__ void overflow_kernel(const void* __restrict__ ei,
                                const float* __restrict__ ew,
                                const float* __restrict__ x, int E) {
    int i = blockIdx.x * blockDim.x + threadIdx.x;
    int cnt = g_ovf_cnt;
    if (cnt > OVF_CAP) cnt = OVF_CAP;
    if (i >= cnt) return;
    int e = g_ovf[i];
    int r, c;
    load_edge(ei, E, e, r, c);
    float w = __ldg(&ew[e]);
    float norm = -dinv_of(g_deg[r]) * w * dinv_of(g_deg[c]);
    const float* xr = x + (size_t)r * D;
    float* t = g_tx1 + (size_t)c * D;
    for (int j = 0; j < D; j++) atomicAdd(&t[j], norm * __ldg(&xr[j]));
}

// ---------------------------------------------------------------------------
// K5 (forked stream): out = x @ W0 + b.  Independent of the edge pipeline.
// ---------------------------------------------------------------------------
__global__ void __launch_bounds__(256)
gemmA_kernel(const float* __restrict__ x,
             const float* __restrict__ W0,
             const float* __restrict__ b,
             float* __restrict__ out, int N) {
    __shared__ __align__(16) float sW[D * D];
    __shared__ __align__(16) float sb[D];
    for (int i = threadIdx.x; i < D * D; i += blockDim.x) sW[i] = W0[i];
    if (threadIdx.x < D) sb[threadIdx.x] = b[threadIdx.x];
    __syncthreads();

    int row = blockIdx.x * blockDim.x + threadIdx.x;
    if (row >= N) return;

    float4 acc[D / 4];
#pragma unroll
    for (int j = 0; j < D / 4; j++) acc[j] = ((const float4*)sb)[j];

    const float4* xr = (const float4*)(x + (size_t)row * D);
#pragma unroll
    for (int k4 = 0; k4 < D / 4; k4++) {
        float4 xv = __ldg(&xr[k4]);
#pragma unroll
        for (int kk = 0; kk < 4; kk++) {
            float xs = (&xv.x)[kk];
            const float4* wr = (const float4*)&sW[(k4 * 4 + kk) * D];
#pragma unroll
            for (int j = 0; j < D / 4; j++) {
                float4 w = wr[j];
                acc[j].x = fmaf(xs, w.x, acc[j].x);
                acc[j].y = fmaf(xs, w.y, acc[j].y);
                acc[j].z = fmaf(xs, w.z, acc[j].z);
                acc[j].w = fmaf(xs, w.w, acc[j].w);
            }
        }
    }
    float4* o = (float4*)(out + (size_t)row * D);
#pragma unroll
    for (int j = 0; j < D / 4; j++) o[j] = acc[j];
}

// ---------------------------------------------------------------------------
// K6 (join): out += Tx1 @ W1.
// ---------------------------------------------------------------------------
__global__ void __launch_bounds__(256)
gemmB_kernel(const float* __restrict__ W1,
             float* __restrict__ out, int N) {
    __shared__ __align__(16) float sW[D * D];
    for (int i = threadIdx.x; i < D * D; i += blockDim.x) sW[i] = W1[i];
    __syncthreads();

    int row = blockIdx.x * blockDim.x + threadIdx.x;
    if (row >= N) return;

    float4* o = (float4*)(out + (size_t)row * D);
    float4 acc[D / 4];
#pragma unroll
    for (int j = 0; j < D / 4; j++) acc[j] = o[j];

    const float4* tr = (const float4*)(g_tx1 + (size_t)row * D);
#pragma unroll
    for (int k4 = 0; k4 < D / 4; k4++) {
        float4 tv = tr[k4];
#pragma unroll
        for (int kk = 0; kk < 4; kk++) {
            float ts = (&tv.x)[kk];
            const float4* wr = (const float4*)&sW[(k4 * 4 + kk) * D];
#pragma unroll
            for (int j = 0; j < D / 4; j++) {
                float4 w = wr[j];
                acc[j].x = fmaf(ts, w.x, acc[j].x);
                acc[j].y = fmaf(ts, w.y, acc[j].y);
                acc[j].z = fmaf(ts, w.z, acc[j].z);
                acc[j].w = fmaf(ts, w.w, acc[j].w);
            }
        }
    }
#pragma unroll
    for (int j = 0; j < D / 4; j++) o[j] = acc[j];
}

// ---------------------------------------------------------------------------
// Launch: fork-join. gemmA (x@W0+b) runs on a side stream concurrently with
// the zero->edge->gather chain; gemmB joins and accumulates Tx1@W1.
// ---------------------------------------------------------------------------
extern "C" void kernel_launch(void* const* d_in, const int* in_sizes, int n_in,
                              void* d_out, int out_size) {
    const float* x  = (const float*)d_in[0];
    const void*  ei = d_in[1];
    const float* ew = (const float*)d_in[2];
    const float* W0 = (const float*)d_in[3];
    const float* W1 = (const float*)d_in[4];
    const float* b  = (const float*)d_in[5];
    float*       out = (float*)d_out;

    int E = in_sizes[2];
    int N = in_sizes[0] / D;

    // One-time infra (no device-memory allocation; identical work every call)
    static cudaStream_t s2 = nullptr;
    static cudaEvent_t evF = nullptr, evJ = nullptr;
    if (s2 == nullptr) {
        cudaStreamCreateWithFlags(&s2, cudaStreamNonBlocking);
        cudaEventCreateWithFlags(&evF, cudaEventDisableTiming);
        cudaEventCreateWithFlags(&evJ, cudaEventDisableTiming);
    }

    // Fork: gemmA depends only on x/W0/b
    cudaEventRecord(evF, 0);
    cudaStreamWaitEvent(s2, evF, 0);
    gemmA_kernel<<<(N + 255) / 256, 256, 0, s2>>>(x, W0, b, out, N);
    cudaEventRecord(evJ, s2);

    // Main chain
    zero_detect_kernel<<<(N_NODES + 255) / 256, 256>>>((const int*)ei);
    edge_pass_kernel<<<(E + 255) / 256, 256>>>(ei, ew, E);
    {
        int warps_per_block = 256 / 32;
        int blocks = (N_NODES + warps_per_block - 1) / warps_per_block;
        gather_kernel<<<blocks, 256>>>(x);
    }
    overflow_kernel<<<(OVF_CAP + 255) / 256, 256>>>(ei, ew, x, E);

    // Join, then accumulate Tx1 @ W1 into out
    cudaStreamWaitEvent(0, evJ, 0);
    gemmB_kernel<<<(N + 255) / 256, 256>>>(W1, out, N);
}

// round 7
// speedup vs baseline: 1.2075x; 1.0469x over previous
#include <cuda_runtime.h>
#include <cstdint>

#define N_NODES 100000
#define D 64
#define CAP 64            // per-node in-edge bucket capacity (Poisson(16), max ~45)
#define OVF_CAP 8192      // overflow edge list (statistically never used)

// Scratch (__device__ globals: allocation-free per harness rules)
__device__ int   g_is64;                          // edge_index dtype flag
__device__ float g_deg[N_NODES];                  // raw weighted out-degree
__device__ int   g_cnt[N_NODES];                  // bucket fill counters
__device__ int2  g_bucket[(size_t)N_NODES * CAP]; // {row, bitcast(w)}
__device__ int   g_ovf_cnt;
__device__ int   g_ovf[OVF_CAP];                  // overflow edge ids
__device__ __align__(16) float g_y[(size_t)N_NODES * D];   // y = x @ W1

__device__ __forceinline__ float dinv_of(float d) {
    return (d > 0.f) ? rsqrtf(d) : 0.f;
}

__device__ __forceinline__ void load_edge(const void* ei, int E, int e,
                                          int& r, int& c) {
    if (g_is64) {
        const long long* p = (const long long*)ei;
        r = (int)p[e];
        c = (int)p[(size_t)E + e];
    } else {
        const int* p = (const int*)ei;
        r = p[e];
        c = p[E + e];
    }
}

// ---------------------------------------------------------------------------
// K1: zero deg + counters; block 0 also detects edge_index dtype.
// ---------------------------------------------------------------------------
__global__ void zero_detect_kernel(const int* __restrict__ ei) {
    int i = blockIdx.x * blockDim.x + threadIdx.x;
    if (i < N_NODES) { g_deg[i] = 0.f; g_cnt[i] = 0; }
    if (i == 0) g_ovf_cnt = 0;
    if (blockIdx.x == 0) {
        __shared__ int any;
        if (threadIdx.x == 0) any = 0;
        __syncthreads();
        int loc = 0;
        for (int k = 1 + 2 * threadIdx.x; k < 4096; k += 2 * blockDim.x)
            loc |= ei[k];
        if (loc) atomicOr(&any, 1);
        __syncthreads();
        if (threadIdx.x == 0) g_is64 = any ? 0 : 1;
    }
}

// ---------------------------------------------------------------------------
// K2: single edge pass — deg[row] += w AND append {row, w} to col's bucket.
// ---------------------------------------------------------------------------
__global__ void edge_pass_kernel(const void* __restrict__ ei,
                                 const float* __restrict__ ew, int E) {
    int e = blockIdx.x * blockDim.x + threadIdx.x;
    if (e >= E) return;
    int r, c;
    load_edge(ei, E, e, r, c);
    float w = __ldg(&ew[e]);
    atomicAdd(&g_deg[r], w);
    int pos = atomicAdd(&g_cnt[c], 1);
    if (pos < CAP) {
        g_bucket[(size_t)c * CAP + pos] = make_int2(r, __float_as_int(w));
    } else {
        int o = atomicAdd(&g_ovf_cnt, 1);
        if (o < OVF_CAP) g_ovf[o] = e;
    }
}

// ---------------------------------------------------------------------------
// Shared GEMM body: dst = src @ W (+ bias), one thread per row.
// ---------------------------------------------------------------------------
template <bool ADD_BIAS>
__device__ __forceinline__ void gemm_row(const float* __restrict__ src,
                                         const float* sW, const float* sb,
                                         float* __restrict__ dst, int row) {
    float4 acc[D / 4];
#pragma unroll
    for (int j = 0; j < D / 4; j++)
        acc[j] = ADD_BIAS ? ((const float4*)sb)[j]
                          : make_float4(0.f, 0.f, 0.f, 0.f);

    const float4* xr = (const float4*)(src + (size_t)row * D);
#pragma unroll
    for (int k4 = 0; k4 < D / 4; k4++) {
        float4 xv = __ldg(&xr[k4]);
#pragma unroll
        for (int kk = 0; kk < 4; kk++) {
            float xs = (&xv.x)[kk];
            const float4* wr = (const float4*)&sW[(k4 * 4 + kk) * D];
#pragma unroll
            for (int j = 0; j < D / 4; j++) {
                float4 w = wr[j];
                acc[j].x = fmaf(xs, w.x, acc[j].x);
                acc[j].y = fmaf(xs, w.y, acc[j].y);
                acc[j].z = fmaf(xs, w.z, acc[j].z);
                acc[j].w = fmaf(xs, w.w, acc[j].w);
            }
        }
    }
    float4* o = (float4*)(dst + (size_t)row * D);
#pragma unroll
    for (int j = 0; j < D / 4; j++) o[j] = acc[j];
}

// K3 (side stream): out = x @ W0 + b
__global__ void __launch_bounds__(256)
gemmA_kernel(const float* __restrict__ x, const float* __restrict__ W0,
             const float* __restrict__ b, float* __restrict__ out, int N) {
    __shared__ __align__(16) float sW[D * D];
    __shared__ __align__(16) float sb[D];
    for (int i = threadIdx.x; i < D * D; i += blockDim.x) sW[i] = W0[i];
    if (threadIdx.x < D) sb[threadIdx.x] = b[threadIdx.x];
    __syncthreads();
    int row = blockIdx.x * blockDim.x + threadIdx.x;
    if (row < N) gemm_row<true>(x, sW, sb, out, row);
}

// K4 (side stream): g_y = x @ W1
__global__ void __launch_bounds__(256)
gemmY_kernel(const float* __restrict__ x, const float* __restrict__ W1, int N) {
    __shared__ __align__(16) float sW[D * D];
    for (int i = threadIdx.x; i < D * D; i += blockDim.x) sW[i] = W1[i];
    __syncthreads();
    int row = blockIdx.x * blockDim.x + threadIdx.x;
    if (row < N) gemm_row<false>(x, sW, nullptr, g_y, row);
}

// ---------------------------------------------------------------------------
// K5: gather. One warp per destination node; lanes own columns lane, lane+32.
//   out[c] += sum_e norm_e * y[r_e]       (y = x @ W1)
// ---------------------------------------------------------------------------
__global__ void __launch_bounds__(256)
gather_kernel(float* __restrict__ out) {
    int warp_in_block = threadIdx.x >> 5;
    int lane = threadIdx.x & 31;
    int node = blockIdx.x * (blockDim.x >> 5) + warp_in_block;
    if (node >= N_NODES) return;

    int n = g_cnt[node];
    if (n > CAP) n = CAP;
    float dinv_c = dinv_of(g_deg[node]);

    float a0 = 0.f, a1 = 0.f;
    const int2* bk = &g_bucket[(size_t)node * CAP];

    for (int base = 0; base < n; base += 32) {
        int m = n - base; if (m > 32) m = 32;
        int   r_l  = 0;
        float nm_l = 0.f;
        if (lane < m) {
            int2 ed = bk[base + lane];
            r_l  = ed.x;
            nm_l = -dinv_of(g_deg[ed.x]) * __int_as_float(ed.y) * dinv_c;
        }
        #pragma unroll 4
        for (int j = 0; j < m; j++) {
            int   r  = __shfl_sync(0xffffffffu, r_l, j);
            float nm = __shfl_sync(0xffffffffu, nm_l, j);
            const float* yr = g_y + (size_t)r * D;
            a0 = fmaf(nm, __ldg(yr + lane),      a0);
            a1 = fmaf(nm, __ldg(yr + 32 + lane), a1);
        }
    }
    float* o = out + (size_t)node * D;
    o[lane]      += a0;
    o[lane + 32] += a1;
}

// ---------------------------------------------------------------------------
// K6: overflow drain (statistically empty) — atomics into out using y.
// ---------------------------------------------------------------------------
__global__ void overflow_kernel(const void* __restrict__ ei,
                                const float* __restrict__ ew,
                                float* __restrict__ out, int E) {
    int i = blockIdx.x * blockDim.x + threadIdx.x;
    int cnt = g_ovf_cnt;
    if (cnt > OVF_CAP) cnt = OVF_CAP;
    if (i >= cnt) return;
    int e = g_ovf[i];
    int r, c;
    load_edge(ei, E, e, r, c);
    float w = __ldg(&ew[e]);
    float norm = -dinv_of(g_deg[r]) * w * dinv_of(g_deg[c]);
    const float* yr = g_y + (size_t)r * D;
    float* o = out + (size_t)c * D;
    for (int j = 0; j < D; j++) atomicAdd(&o[j], norm * __ldg(&yr[j]));
}

// ---------------------------------------------------------------------------
// Launch: side stream computes out=x@W0+b and y=x@W1 concurrently with the
// zero->edge_pass chain; gather joins and accumulates norm-weighted y rows
// straight into out. No gemmB, no tx1 round-trip.
// ---------------------------------------------------------------------------
extern "C" void kernel_launch(void* const* d_in, const int* in_sizes, int n_in,
                              void* d_out, int out_size) {
    const float* x  = (const float*)d_in[0];
    const void*  ei = d_in[1];
    const float* ew = (const float*)d_in[2];
    const float* W0 = (const float*)d_in[3];
    const float* W1 = (const float*)d_in[4];
    const float* b  = (const float*)d_in[5];
    float*       out = (float*)d_out;

    int E = in_sizes[2];
    int N = in_sizes[0] / D;

    static cudaStream_t s2 = nullptr;
    static cudaEvent_t evF = nullptr, evJ = nullptr;
    if (s2 == nullptr) {
        cudaStreamCreateWithFlags(&s2, cudaStreamNonBlocking);
        cudaEventCreateWithFlags(&evF, cudaEventDisableTiming);
        cudaEventCreateWithFlags(&evJ, cudaEventDisableTiming);
    }

    // Fork: both GEMMs depend only on x/W0/W1/b
    cudaEventRecord(evF, 0);
    cudaStreamWaitEvent(s2, evF, 0);
    gemmA_kernel<<<(N + 255) / 256, 256, 0, s2>>>(x, W0, b, out, N);
    gemmY_kernel<<<(N + 255) / 256, 256, 0, s2>>>(x, W1, N);
    cudaEventRecord(evJ, s2);

    // Main chain
    zero_detect_kernel<<<(N_NODES + 255) / 256, 256>>>((const int*)ei);
    edge_pass_kernel<<<(E + 255) / 256, 256>>>(ei, ew, E);

    // Join: gather needs out, y, and the buckets
    cudaStreamWaitEvent(0, evJ, 0);
    {
        int warps_per_block = 256 / 32;
        int blocks = (N_NODES + warps_per_block - 1) / warps_per_block;
        gather_kernel<<<blocks, 256>>>(out);
    }
    overflow_kernel<<<(OVF_CAP + 255) / 256, 256>>>(ei, ew, out, E);
}